// round 11
// baseline (speedup 1.0000x reference)
#include <cuda_runtime.h>
#include <cuda_bf16.h>
#include <math.h>
#include <stdint.h>

#define BB 4
#define LL 4096
#define DD 1024
#define NT (BB*LL)          // 16384 tokens
#define NF 513
#define FS 520
#define NCH 64
#define CHL (LL/NCH)
#define COMPS (NF*2)

// GEMM tiling
#define TM 128
#define TN 128
#define KC 32
#define NKC (DD/KC)         // 32
#define BUF_BYTES (TM*KC*2) // 8192 per operand buffer
#define STG (4*BUF_BYTES)   // 32768 per stage
#define NSTG 3
#define GEMM_SMEM (NSTG*STG) // 96KB

// ---------- scratch ----------
__device__ float  g_keys[NT*DD];
__device__ float  g_vals[NT*DD];
__device__ float2 g_Kf[NT*FS];
__device__ float2 g_P [NT*FS];
__device__ float  g_aux[BB*NCH*COMPS];
__device__ float2 g_twid[512];
__device__ __align__(16) __nv_bfloat16 g_xh[NT*DD],  g_xl[NT*DD];
__device__ __align__(16) __nv_bfloat16 g_rh[NT*DD],  g_rl[NT*DD];
__device__ __align__(16) __nv_bfloat16 g_Wkh[DD*DD], g_Wkl[DD*DD];
__device__ __align__(16) __nv_bfloat16 g_Wvh[DD*DD], g_Wvl[DD*DD];
__device__ __align__(16) __nv_bfloat16 g_Woh[DD*DD], g_Wol[DD*DD];

// ---------- helpers ----------
__device__ __forceinline__ uint32_t smem_u32(const void* p) {
    uint32_t a;
    asm("{ .reg .u64 t; cvta.to.shared.u64 t, %1; cvt.u32.u64 %0, t; }" : "=r"(a) : "l"(p));
    return a;
}
__device__ __forceinline__ uint32_t swz64(uint32_t off) {
    return off ^ ((off >> 3) & 0x30);
}
__device__ __forceinline__ void ldm_x4(uint32_t* r, uint32_t addr) {
    asm volatile("ldmatrix.sync.aligned.m8n8.x4.shared.b16 {%0,%1,%2,%3}, [%4];"
        : "=r"(r[0]), "=r"(r[1]), "=r"(r[2]), "=r"(r[3]) : "r"(addr));
}
__device__ __forceinline__ void mma16816(float* d, const uint32_t* a, const uint32_t* b) {
    asm volatile("mma.sync.aligned.m16n8k16.row.col.f32.bf16.bf16.f32 "
        "{%0,%1,%2,%3}, {%4,%5,%6,%7}, {%8,%9}, {%0,%1,%2,%3};"
        : "+f"(d[0]), "+f"(d[1]), "+f"(d[2]), "+f"(d[3])
        : "r"(a[0]), "r"(a[1]), "r"(a[2]), "r"(a[3]), "r"(b[0]), "r"(b[1]));
}
__device__ __forceinline__ void cp16(uint32_t dst, const void* src) {
    asm volatile("cp.async.cg.shared.global [%0], [%1], 16;" :: "r"(dst), "l"(src));
}

// ---------- twiddles ----------
__global__ void init_twid() {
    int t = threadIdx.x;
    double a = -2.0 * M_PI * (double)t / 1024.0;
    g_twid[t] = make_float2((float)cos(a), (float)sin(a));
}

__device__ __forceinline__ float2 cmul(float2 a, float2 b) {
    return make_float2(a.x*b.x - a.y*b.y, a.x*b.y + a.y*b.x);
}
__device__ __forceinline__ float2 cadd(float2 a, float2 b) { return make_float2(a.x+b.x, a.y+b.y); }
__device__ __forceinline__ float2 csub(float2 a, float2 b) { return make_float2(a.x-b.x, a.y-b.y); }
__device__ __forceinline__ float2 cmw(float2 d, float wx, float wy) {
    return make_float2(d.x*wx - d.y*wy, d.x*wy + d.y*wx);
}

// ---------- radix-2^2 Stockham FFT: 2*NH points, NH/2 lanes ----------
template<int NH, int TS>
__device__ __forceinline__ float2* fft_r22(float2* s0, float2* s1, int j, bool inverse) {
    const int NQ = NH / 2;
    float2* src = s0;
    float2* dst = s1;
    #pragma unroll
    for (int m = 1; m <= NQ; m <<= 2) {
        int jm = j & ~(m - 1);
        float2 a = src[j], b = src[j + NQ], c = src[j + NH], d = src[j + NQ + NH];
        float2 w1 = g_twid[jm * TS];
        float2 w2 = g_twid[(jm + NQ) * TS];
        float w1y = inverse ? -w1.y : w1.y;
        float w2y = inverse ? -w2.y : w2.y;
        float2 sv1 = cadd(a, c);
        float2 tv1 = cmw(csub(a, c), w1.x, w1y);
        float2 sv2 = cadd(b, d);
        float2 tv2 = cmw(csub(b, d), w2.x, w2y);
        int p1 = j + jm;
        int p2 = p1 + m;
        int jmA = p1 & ~(2*m - 1);
        int jmB = p2 & ~(2*m - 1);
        float2 wA = g_twid[jmA * TS];
        float2 wB = g_twid[jmB * TS];
        float wAy = inverse ? -wA.y : wA.y;
        float wBy = inverse ? -wB.y : wB.y;
        dst[p1 + jmA]         = cadd(sv1, sv2);
        dst[p1 + jmA + 2*m]   = cmw(csub(sv1, sv2), wA.x, wAy);
        dst[p2 + jmB]         = cadd(tv1, tv2);
        dst[p2 + jmB + 2*m]   = cmw(csub(tv1, tv2), wB.x, wBy);
        __syncthreads();
        float2* tp = src; src = dst; dst = tp;
    }
    return src;
}

// ---------- fp32 -> bf16 hi/lo split ----------
__global__ void __launch_bounds__(256) conv_split(const float* __restrict__ src,
                                                  __nv_bfloat16* __restrict__ hi,
                                                  __nv_bfloat16* __restrict__ lo, int n4) {
    int i = blockIdx.x * blockDim.x + threadIdx.x;
    if (i >= n4) return;
    float4 v = ((const float4*)src)[i];
    __nv_bfloat16 h0 = __float2bfloat16_rn(v.x), h1 = __float2bfloat16_rn(v.y);
    __nv_bfloat16 h2 = __float2bfloat16_rn(v.z), h3 = __float2bfloat16_rn(v.w);
    __nv_bfloat16 l0 = __float2bfloat16_rn(v.x - __bfloat162float(h0));
    __nv_bfloat16 l1 = __float2bfloat16_rn(v.y - __bfloat162float(h1));
    __nv_bfloat16 l2 = __float2bfloat16_rn(v.z - __bfloat162float(h2));
    __nv_bfloat16 l3 = __float2bfloat16_rn(v.w - __bfloat162float(h3));
    __nv_bfloat162* H = (__nv_bfloat162*)hi;
    __nv_bfloat162* L = (__nv_bfloat162*)lo;
    H[i*2]   = __nv_bfloat162(h0, h1);
    H[i*2+1] = __nv_bfloat162(h2, h3);
    L[i*2]   = __nv_bfloat162(l0, l1);
    L[i*2+1] = __nv_bfloat162(l2, l3);
}

// ---------- HMMA bf16-split GEMM, 3-stage pipeline, loads issued before compute ----------
__global__ void __launch_bounds__(256, 2) gemm_bf16(
    const __nv_bfloat16* __restrict__ Ah, const __nv_bfloat16* __restrict__ Al,
    const __nv_bfloat16* __restrict__ Bh, const __nv_bfloat16* __restrict__ Bl,
    const float* __restrict__ bias, const float* __restrict__ resid,
    float* __restrict__ C)
{
    extern __shared__ char smem[];
    uint32_t sb = smem_u32(smem);
    int tid = threadIdx.x, lane = tid & 31, wid = tid >> 5;
    int wm = wid >> 2, wn = wid & 3;
    int m0 = blockIdx.y * TM, n0 = blockIdx.x * TN;

    const __nv_bfloat16* srcs[4] = {Ah, Al, Bh, Bl};
    const int rb[4] = {m0, m0, n0, n0};

    float acc[4][4][4];
    #pragma unroll
    for (int i = 0; i < 4; i++)
        #pragma unroll
        for (int j = 0; j < 4; j++)
            #pragma unroll
            for (int k = 0; k < 4; k++) acc[i][j][k] = 0.f;

    // one K-chunk (KC=32 cols, 64B rows) into stage st
    auto load_chunk = [&](int kc, int st) {
        #pragma unroll
        for (int i = 0; i < 2; i++) {
            int ch = tid + i * 256;             // 512 16B-chunks per buffer
            int row = ch >> 2, c4 = ch & 3;
            uint32_t swo = swz64((uint32_t)(row * 64 + c4 * 16));
            #pragma unroll
            for (int bu = 0; bu < 4; bu++) {
                const void* g = srcs[bu] + (size_t)(rb[bu] + row) * DD + kc * KC + c4 * 8;
                cp16(sb + st * STG + bu * BUF_BYTES + swo, g);
            }
        }
        asm volatile("cp.async.commit_group;" ::: "memory");
    };

    load_chunk(0, 0);
    load_chunk(1, 1);

    for (int kc = 0; kc < NKC; kc++) {
        if (kc >= NKC - 1) asm volatile("cp.async.wait_group 0;" ::: "memory");
        else               asm volatile("cp.async.wait_group 1;" ::: "memory");
        __syncthreads();

        // issue next loads BEFORE compute so they overlap the MMAs
        if (kc + 2 < NKC) load_chunk(kc + 2, (kc + 2) % NSTG);

        int st = kc % NSTG;
        uint32_t aHb = sb + st * STG;
        uint32_t aLb = aHb + BUF_BYTES;
        uint32_t bHb = aHb + 2 * BUF_BYTES;
        uint32_t bLb = aHb + 3 * BUF_BYTES;

        int grp = lane >> 3;
        #pragma unroll
        for (int ks = 0; ks < 2; ks++) {
            uint32_t ah[4][4], al[4][4], bh[2][4], bl[2][4];
            #pragma unroll
            for (int mt = 0; mt < 4; mt++) {
                uint32_t off = swz64((uint32_t)((wm*64 + mt*16 + (lane & 15)) * 64
                                              + ks*32 + (lane >> 4) * 16));
                ldm_x4(ah[mt], aHb + off);
                ldm_x4(al[mt], aLb + off);
            }
            #pragma unroll
            for (int nt2 = 0; nt2 < 2; nt2++) {
                uint32_t off = swz64((uint32_t)((wn*32 + nt2*16 + (grp >> 1)*8 + (lane & 7)) * 64
                                              + ks*32 + (grp & 1) * 16));
                ldm_x4(bh[nt2], bHb + off);
                ldm_x4(bl[nt2], bLb + off);
            }
            #pragma unroll
            for (int mt = 0; mt < 4; mt++)
                #pragma unroll
                for (int nt = 0; nt < 4; nt++) {
                    const uint32_t* bhf = &bh[nt >> 1][(nt & 1) * 2];
                    const uint32_t* blf = &bl[nt >> 1][(nt & 1) * 2];
                    mma16816(acc[mt][nt], ah[mt], bhf);
                    mma16816(acc[mt][nt], ah[mt], blf);
                    mma16816(acc[mt][nt], al[mt], bhf);
                }
        }
    }

    #pragma unroll
    for (int mt = 0; mt < 4; mt++) {
        int row0 = m0 + wm*64 + mt*16 + (lane >> 2);
        #pragma unroll
        for (int nt = 0; nt < 4; nt++) {
            int col = n0 + wn*32 + nt*8 + (lane & 3) * 2;
            float2 bi = *(const float2*)&bias[col];
            size_t o0 = (size_t)row0 * DD + col;
            size_t o1 = (size_t)(row0 + 8) * DD + col;
            float2 v0 = make_float2(acc[mt][nt][0] + bi.x, acc[mt][nt][1] + bi.y);
            float2 v1 = make_float2(acc[mt][nt][2] + bi.x, acc[mt][nt][3] + bi.y);
            if (resid) {
                float2 r0 = *(const float2*)(resid + o0);
                float2 r1 = *(const float2*)(resid + o1);
                v0.x += r0.x; v0.y += r0.y;
                v1.x += r1.x; v1.y += r1.y;
            }
            *(float2*)(C + o0) = v0;
            *(float2*)(C + o1) = v1;
        }
    }
}

// ---------- fwd: pack k+iv, one 1024-pt radix-2^2 FFT, 2 tokens/block ----------
__global__ void __launch_bounds__(512) fwd_kernel() {
    __shared__ float2 s0[2][1024];
    __shared__ float2 s1[2][1024];
    __shared__ float red[2][8];
    int tid = threadIdx.x;
    int half = tid >> 8, j = tid & 255;
    int t = blockIdx.x * 2 + half;

    const float* kr = g_keys + (size_t)t * DD;
    const float* vr = g_vals + (size_t)t * DD;
    float kv[4], vv[4];
    #pragma unroll
    for (int q = 0; q < 4; q++) { kv[q] = kr[j + q*256]; vv[q] = vr[j + q*256]; }

    float ss = kv[0]*kv[0] + kv[1]*kv[1] + kv[2]*kv[2] + kv[3]*kv[3];
    #pragma unroll
    for (int o = 16; o; o >>= 1) ss += __shfl_xor_sync(0xffffffffu, ss, o);
    if ((tid & 31) == 0) red[half][(tid >> 5) & 7] = ss;
    __syncthreads();
    float tot = 0.f;
    #pragma unroll
    for (int i = 0; i < 8; i++) tot += red[half][i];
    float scl = 1.0f / fmaxf(sqrtf(tot), 1e-12f);

    #pragma unroll
    for (int q = 0; q < 4; q++)
        s0[half][j + q*256] = make_float2(kv[q] * scl, vv[q]);
    __syncthreads();

    float2* Z = fft_r22<512, 1>(s0[half], s1[half], j, false);

    size_t fb = (size_t)t * FS;
    #pragma unroll
    for (int sel = 0; sel < 2; sel++) {
        int b = sel ? (512 - j) : j;
        float2 za = Z[b];
        float2 zb = Z[(1024 - b) & 1023];
        float2 Kf = make_float2(0.5f * (za.x + zb.x), 0.5f * (za.y - zb.y));
        float2 dv = make_float2(za.x - zb.x, za.y + zb.y);
        float2 Vf = make_float2(0.5f * dv.y, -0.5f * dv.x);
        g_Kf[fb + b] = Kf;
        g_P [fb + b] = cmul(Kf, Vf);
    }
    if (j == 0) {
        float2 za = Z[256], zb = Z[768];
        float2 Kf = make_float2(0.5f * (za.x + zb.x), 0.5f * (za.y - zb.y));
        float2 dv = make_float2(za.x - zb.x, za.y + zb.y);
        float2 Vf = make_float2(0.5f * dv.y, -0.5f * dv.x);
        g_Kf[fb + 256] = Kf;
        g_P [fb + 256] = cmul(Kf, Vf);
    }
}

// ---------- scan pass 1: intra-chunk cumsum + chunk totals ----------
__global__ void __launch_bounds__(256) scan1() {
    int idx = blockIdx.x * blockDim.x + threadIdx.x;
    int comp  = idx % COMPS;
    int rest  = idx / COMPS;
    int chunk = rest % NCH;
    int b     = rest / NCH;
    float* Pf = (float*)g_P;
    size_t base = (size_t)(b * LL + chunk * CHL) * (FS * 2) + comp;
    float acc = 0.f;
    #pragma unroll 4
    for (int s = 0; s < CHL; s++) {
        acc += Pf[base];
        Pf[base] = acc;
        base += FS * 2;
    }
    g_aux[(b * NCH + chunk) * COMPS + comp] = acc;
}

// ---------- aux exclusive prefix scan (in place) ----------
__global__ void __launch_bounds__(256) aux_scan() {
    int idx = blockIdx.x * blockDim.x + threadIdx.x;
    if (idx >= BB * COMPS) return;
    int b = idx / COMPS, comp = idx % COMPS;
    float run = 0.f;
    for (int c = 0; c < NCH; c++) {
        size_t a = (size_t)(b * NCH + c) * COMPS + comp;
        float v = g_aux[a];
        g_aux[a] = run;
        run += v;
    }
}

// ---------- inv: unbind (+chunk offset), 512-pt radix-2^2 irfft, LN -> bf16 ----------
__global__ void __launch_bounds__(512) inv_kernel(const float* __restrict__ ln_g,
                                                  const float* __restrict__ ln_b) {
    __shared__ float2 sA[4][520];
    __shared__ float2 sB[4][512];
    __shared__ float red[4][8];
    int tid = threadIdx.x;
    int q = tid >> 7, j = tid & 127;
    int t = blockIdx.x * 4 + q;
    size_t fb = (size_t)t * FS;
    int bI = t >> 12;
    int chunk = (t & (LL - 1)) >> 6;
    const float2* aux2 = (const float2*)g_aux + (size_t)(bI * NCH + chunk) * (COMPS/2);

    #pragma unroll
    for (int p = 0; p < 4; p++) {
        int k = j + p * 128;
        float2 kf = g_Kf[fb + k];
        float2 mp = g_P [fb + k];
        float2 av = aux2[k];
        mp.x += av.x; mp.y += av.y;
        sA[q][k] = make_float2(mp.x*kf.x + mp.y*kf.y, mp.y*kf.x - mp.x*kf.y);
    }
    if (j == 0) {
        float2 kf = g_Kf[fb + 512];
        float2 mp = g_P [fb + 512];
        float2 av = aux2[512];
        mp.x += av.x; mp.y += av.y;
        sA[q][512] = make_float2(mp.x*kf.x + mp.y*kf.y, mp.y*kf.x - mp.x*kf.y);
    }
    __syncthreads();

    #pragma unroll
    for (int p = 0; p < 4; p++) {
        int k = j + p * 128;
        float2 Sa = sA[q][k];
        float2 Sb = sA[q][512 - k];
        float2 tw = g_twid[k];
        float twx = tw.x, twy = -tw.y;
        float2 Xe = make_float2(0.5f*(Sa.x + Sb.x), 0.5f*(Sa.y - Sb.y));
        float2 Xd = make_float2(0.5f*(Sa.x - Sb.x), 0.5f*(Sa.y + Sb.y));
        float2 Xo = make_float2(Xd.x*twx - Xd.y*twy, Xd.x*twy + Xd.y*twx);
        sB[q][k] = make_float2(Xe.x - Xo.y, Xe.y + Xo.x);
    }
    __syncthreads();

    float2* R = fft_r22<256, 2>(sB[q], sA[q], j, true);

    float2 Ra = R[j], Rb = R[j + 256], Rc = R[j + 128], Rd = R[j + 384];
    float2 z[4];
    int    zi[4];
    z[0] = cadd(Ra, Rb); zi[0] = j;
    z[1] = csub(Ra, Rb); zi[1] = j + 256;
    z[2] = cadd(Rc, Rd); zi[2] = j + 128;
    z[3] = csub(Rc, Rd); zi[3] = j + 384;

    int pos = (t & (LL - 1)) + 1;
    float scale = rsqrtf((float)pos) * (1.0f / 512.0f);
    float r[8];
    #pragma unroll
    for (int p = 0; p < 4; p++) { r[2*p] = z[p].x * scale; r[2*p+1] = z[p].y * scale; }

    float sm = 0.f, sq = 0.f;
    #pragma unroll
    for (int p = 0; p < 8; p++) { sm += r[p]; sq += r[p]*r[p]; }
    #pragma unroll
    for (int o = 16; o; o >>= 1) {
        sm += __shfl_xor_sync(0xffffffffu, sm, o);
        sq += __shfl_xor_sync(0xffffffffu, sq, o);
    }
    int w4 = (tid >> 5) & 3;
    if ((tid & 31) == 0) { red[q][w4] = sm; red[q][4 + w4] = sq; }
    __syncthreads();
    float smT = 0.f, sqT = 0.f;
    #pragma unroll
    for (int i = 0; i < 4; i++) { smT += red[q][i]; sqT += red[q][4 + i]; }
    float mu  = smT * (1.0f / 1024.0f);
    float var = sqT * (1.0f / 1024.0f) - mu * mu;
    float rstd = rsqrtf(var + 1e-5f);

    __nv_bfloat162* RH = (__nv_bfloat162*)g_rh;
    __nv_bfloat162* RL = (__nv_bfloat162*)g_rl;
    size_t hb = (size_t)t * 512;
    #pragma unroll
    for (int p = 0; p < 4; p++) {
        int idx = zi[p];
        float2 gg = *(const float2*)&ln_g[2*idx];
        float2 bb = *(const float2*)&ln_b[2*idx];
        float y0 = (r[2*p]   - mu) * rstd * gg.x + bb.x;
        float y1 = (r[2*p+1] - mu) * rstd * gg.y + bb.y;
        __nv_bfloat16 h0 = __float2bfloat16_rn(y0);
        __nv_bfloat16 h1 = __float2bfloat16_rn(y1);
        RH[hb + idx] = __nv_bfloat162(h0, h1);
        RL[hb + idx] = __nv_bfloat162(__float2bfloat16_rn(y0 - __bfloat162float(h0)),
                                      __float2bfloat16_rn(y1 - __bfloat162float(h1)));
    }
}

// ---------- launch ----------
extern "C" void kernel_launch(void* const* d_in, const int* in_sizes, int n_in,
                              void* d_out, int out_size) {
    const float* x    = (const float*)d_in[0];
    const float* Wk   = (const float*)d_in[1];
    const float* bk   = (const float*)d_in[2];
    const float* Wv   = (const float*)d_in[3];
    const float* bv   = (const float*)d_in[4];
    const float* ln_g = (const float*)d_in[5];
    const float* ln_b = (const float*)d_in[6];
    const float* Wo   = (const float*)d_in[7];
    const float* bo   = (const float*)d_in[8];
    float* out = (float*)d_out;

    float *keys, *vals;
    __nv_bfloat16 *xh, *xl, *rh, *rl, *wkh, *wkl, *wvh, *wvl, *woh, *wol;
    cudaGetSymbolAddress((void**)&keys, g_keys);
    cudaGetSymbolAddress((void**)&vals, g_vals);
    cudaGetSymbolAddress((void**)&xh, g_xh);   cudaGetSymbolAddress((void**)&xl, g_xl);
    cudaGetSymbolAddress((void**)&rh, g_rh);   cudaGetSymbolAddress((void**)&rl, g_rl);
    cudaGetSymbolAddress((void**)&wkh, g_Wkh); cudaGetSymbolAddress((void**)&wkl, g_Wkl);
    cudaGetSymbolAddress((void**)&wvh, g_Wvh); cudaGetSymbolAddress((void**)&wvl, g_Wvl);
    cudaGetSymbolAddress((void**)&woh, g_Woh); cudaGetSymbolAddress((void**)&wol, g_Wol);

    cudaFuncSetAttribute(gemm_bf16, cudaFuncAttributeMaxDynamicSharedMemorySize, GEMM_SMEM);

    // launch order arranged so slots 5 & 6 are gemm_bf16 (for ncu -s 5 -c 1)
    init_twid<<<1, 512>>>();                                            // 1
    conv_split<<<(NT*DD/4 + 255)/256, 256>>>(x,  xh,  xl,  NT*DD/4);    // 2
    conv_split<<<(DD*DD/4 + 255)/256, 256>>>(Wk, wkh, wkl, DD*DD/4);    // 3
    conv_split<<<(DD*DD/4 + 255)/256, 256>>>(Wv, wvh, wvl, DD*DD/4);    // 4

    dim3 gg(8, NT / TM);  // (8, 128)
    gemm_bf16<<<gg, 256, GEMM_SMEM>>>(xh, xl, wkh, wkl, bk, nullptr, keys);  // 5
    gemm_bf16<<<gg, 256, GEMM_SMEM>>>(xh, xl, wvh, wvl, bv, nullptr, vals);  // 6

    conv_split<<<(DD*DD/4 + 255)/256, 256>>>(Wo, woh, wol, DD*DD/4);    // 7

    fwd_kernel<<<NT/2, 512>>>();                                        // 8
    scan1<<<(BB * NCH * COMPS) / 256, 256>>>();                         // 9
    aux_scan<<<(BB * COMPS + 255) / 256, 256>>>();                      // 10
    inv_kernel<<<NT/4, 512>>>(ln_g, ln_b);                              // 11

    gemm_bf16<<<gg, 256, GEMM_SMEM>>>(rh, rl, woh, wol, bo, x, out);    // 12
}

// round 14
// speedup vs baseline: 1.0370x; 1.0370x over previous
#include <cuda_runtime.h>
#include <cuda_bf16.h>
#include <math.h>
#include <stdint.h>

#define BB 4
#define LL 4096
#define DD 1024
#define NT (BB*LL)          // 16384 tokens
#define NF 513
#define FS 520
#define NCH 64
#define CHL (LL/NCH)
#define COMPS (NF*2)

// GEMM tiling: 128x128 tile, KC=64, 3-stage pipeline
#define TM 128
#define TN 128
#define KC 64
#define NKC (DD/KC)         // 16
#define BUF_BYTES (TM*KC*2) // 16384 per operand buffer
#define STG (4*BUF_BYTES)   // 65536 per stage
#define NSTG 3
#define GEMM_SMEM (NSTG*STG) // 192KB

// ---------- scratch ----------
__device__ float  g_keys[NT*DD];
__device__ float  g_vals[NT*DD];
__device__ float2 g_Kf[NT*FS];
__device__ float2 g_P [NT*FS];
__device__ float  g_aux[BB*NCH*COMPS];
__device__ float2 g_twid[512];
__device__ __align__(16) __nv_bfloat16 g_xh[NT*DD],  g_xl[NT*DD];
__device__ __align__(16) __nv_bfloat16 g_rh[NT*DD],  g_rl[NT*DD];
__device__ __align__(16) __nv_bfloat16 g_Wkh[DD*DD], g_Wkl[DD*DD];
__device__ __align__(16) __nv_bfloat16 g_Wvh[DD*DD], g_Wvl[DD*DD];
__device__ __align__(16) __nv_bfloat16 g_Woh[DD*DD], g_Wol[DD*DD];

// ---------- helpers ----------
__device__ __forceinline__ uint32_t smem_u32(const void* p) {
    uint32_t a;
    asm("{ .reg .u64 t; cvta.to.shared.u64 t, %1; cvt.u32.u64 %0, t; }" : "=r"(a) : "l"(p));
    return a;
}
__device__ __forceinline__ uint32_t swz(uint32_t off) {
    return off ^ ((off >> 3) & 0x70);
}
__device__ __forceinline__ void ldm_x4(uint32_t* r, uint32_t addr) {
    asm volatile("ldmatrix.sync.aligned.m8n8.x4.shared.b16 {%0,%1,%2,%3}, [%4];"
        : "=r"(r[0]), "=r"(r[1]), "=r"(r[2]), "=r"(r[3]) : "r"(addr));
}
__device__ __forceinline__ void mma16816(float* d, const uint32_t* a, const uint32_t* b) {
    asm volatile("mma.sync.aligned.m16n8k16.row.col.f32.bf16.bf16.f32 "
        "{%0,%1,%2,%3}, {%4,%5,%6,%7}, {%8,%9}, {%0,%1,%2,%3};"
        : "+f"(d[0]), "+f"(d[1]), "+f"(d[2]), "+f"(d[3])
        : "r"(a[0]), "r"(a[1]), "r"(a[2]), "r"(a[3]), "r"(b[0]), "r"(b[1]));
}
__device__ __forceinline__ void cp16(uint32_t dst, const void* src) {
    asm volatile("cp.async.cg.shared.global [%0], [%1], 16;" :: "r"(dst), "l"(src));
}

// ---------- twiddles ----------
__global__ void init_twid() {
    int t = threadIdx.x;
    double a = -2.0 * M_PI * (double)t / 1024.0;
    g_twid[t] = make_float2((float)cos(a), (float)sin(a));
}

__device__ __forceinline__ float2 cmul(float2 a, float2 b) {
    return make_float2(a.x*b.x - a.y*b.y, a.x*b.y + a.y*b.x);
}
__device__ __forceinline__ float2 cadd(float2 a, float2 b) { return make_float2(a.x+b.x, a.y+b.y); }
__device__ __forceinline__ float2 csub(float2 a, float2 b) { return make_float2(a.x-b.x, a.y-b.y); }
__device__ __forceinline__ float2 cmw(float2 d, float wx, float wy) {
    return make_float2(d.x*wx - d.y*wy, d.x*wy + d.y*wx);
}

// ---------- radix-2^2 Stockham FFT: 2*NH points, NH/2 lanes ----------
template<int NH, int TS>
__device__ __forceinline__ float2* fft_r22(float2* s0, float2* s1, int j, bool inverse) {
    const int NQ = NH / 2;
    float2* src = s0;
    float2* dst = s1;
    #pragma unroll
    for (int m = 1; m <= NQ; m <<= 2) {
        int jm = j & ~(m - 1);
        float2 a = src[j], b = src[j + NQ], c = src[j + NH], d = src[j + NQ + NH];
        float2 w1 = g_twid[jm * TS];
        float2 w2 = g_twid[(jm + NQ) * TS];
        float w1y = inverse ? -w1.y : w1.y;
        float w2y = inverse ? -w2.y : w2.y;
        float2 sv1 = cadd(a, c);
        float2 tv1 = cmw(csub(a, c), w1.x, w1y);
        float2 sv2 = cadd(b, d);
        float2 tv2 = cmw(csub(b, d), w2.x, w2y);
        int p1 = j + jm;
        int p2 = p1 + m;
        int jmA = p1 & ~(2*m - 1);
        int jmB = p2 & ~(2*m - 1);
        float2 wA = g_twid[jmA * TS];
        float2 wB = g_twid[jmB * TS];
        float wAy = inverse ? -wA.y : wA.y;
        float wBy = inverse ? -wB.y : wB.y;
        dst[p1 + jmA]         = cadd(sv1, sv2);
        dst[p1 + jmA + 2*m]   = cmw(csub(sv1, sv2), wA.x, wAy);
        dst[p2 + jmB]         = cadd(tv1, tv2);
        dst[p2 + jmB + 2*m]   = cmw(csub(tv1, tv2), wB.x, wBy);
        __syncthreads();
        float2* tp = src; src = dst; dst = tp;
    }
    return src;
}

// ---------- fp32 -> bf16 hi/lo split ----------
__global__ void __launch_bounds__(256) conv_split(const float* __restrict__ src,
                                                  __nv_bfloat16* __restrict__ hi,
                                                  __nv_bfloat16* __restrict__ lo, int n4) {
    int i = blockIdx.x * blockDim.x + threadIdx.x;
    if (i >= n4) return;
    float4 v = ((const float4*)src)[i];
    __nv_bfloat16 h0 = __float2bfloat16_rn(v.x), h1 = __float2bfloat16_rn(v.y);
    __nv_bfloat16 h2 = __float2bfloat16_rn(v.z), h3 = __float2bfloat16_rn(v.w);
    __nv_bfloat16 l0 = __float2bfloat16_rn(v.x - __bfloat162float(h0));
    __nv_bfloat16 l1 = __float2bfloat16_rn(v.y - __bfloat162float(h1));
    __nv_bfloat16 l2 = __float2bfloat16_rn(v.z - __bfloat162float(h2));
    __nv_bfloat16 l3 = __float2bfloat16_rn(v.w - __bfloat162float(h3));
    __nv_bfloat162* H = (__nv_bfloat162*)hi;
    __nv_bfloat162* L = (__nv_bfloat162*)lo;
    H[i*2]   = __nv_bfloat162(h0, h1);
    H[i*2+1] = __nv_bfloat162(h2, h3);
    L[i*2]   = __nv_bfloat162(l0, l1);
    L[i*2+1] = __nv_bfloat162(l2, l3);
}

// ---------- HMMA bf16-split GEMM: 3-stage, KC=64, loads before compute ----------
__global__ void __launch_bounds__(256, 1) gemm_bf16(
    const __nv_bfloat16* __restrict__ Ah, const __nv_bfloat16* __restrict__ Al,
    const __nv_bfloat16* __restrict__ Bh, const __nv_bfloat16* __restrict__ Bl,
    const float* __restrict__ bias, const float* __restrict__ resid,
    float* __restrict__ C)
{
    extern __shared__ char smem[];
    uint32_t sb = smem_u32(smem);
    int tid = threadIdx.x, lane = tid & 31, wid = tid >> 5;
    int wm = wid >> 2, wn = wid & 3;
    int m0 = blockIdx.y * TM, n0 = blockIdx.x * TN;

    const __nv_bfloat16* srcs[4] = {Ah, Al, Bh, Bl};
    const int rb[4] = {m0, m0, n0, n0};

    float acc[4][4][4];
    #pragma unroll
    for (int i = 0; i < 4; i++)
        #pragma unroll
        for (int j = 0; j < 4; j++)
            #pragma unroll
            for (int k = 0; k < 4; k++) acc[i][j][k] = 0.f;

    // one K-chunk (KC=64 cols, 128B rows, SW128) into stage st
    auto load_chunk = [&](int kc, int st) {
        #pragma unroll
        for (int i = 0; i < 4; i++) {
            int ch = tid + i * 256;             // 1024 16B-chunks per buffer
            int row = ch >> 3, j = ch & 7;
            uint32_t swo = swz((uint32_t)(row * 128 + j * 16));
            #pragma unroll
            for (int bu = 0; bu < 4; bu++) {
                const void* g = srcs[bu] + (size_t)(rb[bu] + row) * DD + kc * KC + j * 8;
                cp16(sb + st * STG + bu * BUF_BYTES + swo, g);
            }
        }
        asm volatile("cp.async.commit_group;" ::: "memory");
    };

    load_chunk(0, 0);
    load_chunk(1, 1);

    for (int kc = 0; kc < NKC; kc++) {
        if (kc == NKC - 1) asm volatile("cp.async.wait_group 0;" ::: "memory");
        else               asm volatile("cp.async.wait_group 1;" ::: "memory");
        __syncthreads();

        // issue next loads BEFORE compute so they overlap the MMAs
        if (kc + 2 < NKC) load_chunk(kc + 2, (kc + 2) % NSTG);

        int st = kc % NSTG;
        uint32_t aHb = sb + st * STG;
        uint32_t aLb = aHb + BUF_BYTES;
        uint32_t bHb = aHb + 2 * BUF_BYTES;
        uint32_t bLb = aHb + 3 * BUF_BYTES;

        int grp = lane >> 3;
        #pragma unroll
        for (int ks = 0; ks < 4; ks++) {
            uint32_t ah[4][4], al[4][4], bh[2][4], bl[2][4];
            #pragma unroll
            for (int mt = 0; mt < 4; mt++) {
                uint32_t off = swz((uint32_t)((wm*64 + mt*16 + (lane & 15)) * 128
                                              + ks*32 + (lane >> 4) * 16));
                ldm_x4(ah[mt], aHb + off);
                ldm_x4(al[mt], aLb + off);
            }
            #pragma unroll
            for (int nt2 = 0; nt2 < 2; nt2++) {
                uint32_t off = swz((uint32_t)((wn*32 + nt2*16 + (grp >> 1)*8 + (lane & 7)) * 128
                                              + ks*32 + (grp & 1) * 16));
                ldm_x4(bh[nt2], bHb + off);
                ldm_x4(bl[nt2], bLb + off);
            }
            #pragma unroll
            for (int mt = 0; mt < 4; mt++)
                #pragma unroll
                for (int nt = 0; nt < 4; nt++) {
                    const uint32_t* bhf = &bh[nt >> 1][(nt & 1) * 2];
                    const uint32_t* blf = &bl[nt >> 1][(nt & 1) * 2];
                    mma16816(acc[mt][nt], ah[mt], bhf);
                    mma16816(acc[mt][nt], ah[mt], blf);
                    mma16816(acc[mt][nt], al[mt], bhf);
                }
        }
    }

    #pragma unroll
    for (int mt = 0; mt < 4; mt++) {
        int row0 = m0 + wm*64 + mt*16 + (lane >> 2);
        #pragma unroll
        for (int nt = 0; nt < 4; nt++) {
            int col = n0 + wn*32 + nt*8 + (lane & 3) * 2;
            float2 bi = *(const float2*)&bias[col];
            size_t o0 = (size_t)row0 * DD + col;
            size_t o1 = (size_t)(row0 + 8) * DD + col;
            float2 v0 = make_float2(acc[mt][nt][0] + bi.x, acc[mt][nt][1] + bi.y);
            float2 v1 = make_float2(acc[mt][nt][2] + bi.x, acc[mt][nt][3] + bi.y);
            if (resid) {
                float2 r0 = *(const float2*)(resid + o0);
                float2 r1 = *(const float2*)(resid + o1);
                v0.x += r0.x; v0.y += r0.y;
                v1.x += r1.x; v1.y += r1.y;
            }
            *(float2*)(C + o0) = v0;
            *(float2*)(C + o1) = v1;
        }
    }
}

// ---------- fwd: pack k+iv, one 1024-pt radix-2^2 FFT, 2 tokens/block ----------
__global__ void __launch_bounds__(512) fwd_kernel() {
    __shared__ float2 s0[2][1024];
    __shared__ float2 s1[2][1024];
    __shared__ float red[2][8];
    int tid = threadIdx.x;
    int half = tid >> 8, j = tid & 255;
    int t = blockIdx.x * 2 + half;

    const float* kr = g_keys + (size_t)t * DD;
    const float* vr = g_vals + (size_t)t * DD;
    float kv[4], vv[4];
    #pragma unroll
    for (int q = 0; q < 4; q++) { kv[q] = kr[j + q*256]; vv[q] = vr[j + q*256]; }

    float ss = kv[0]*kv[0] + kv[1]*kv[1] + kv[2]*kv[2] + kv[3]*kv[3];
    #pragma unroll
    for (int o = 16; o; o >>= 1) ss += __shfl_xor_sync(0xffffffffu, ss, o);
    if ((tid & 31) == 0) red[half][(tid >> 5) & 7] = ss;
    __syncthreads();
    float tot = 0.f;
    #pragma unroll
    for (int i = 0; i < 8; i++) tot += red[half][i];
    float scl = 1.0f / fmaxf(sqrtf(tot), 1e-12f);

    #pragma unroll
    for (int q = 0; q < 4; q++)
        s0[half][j + q*256] = make_float2(kv[q] * scl, vv[q]);
    __syncthreads();

    float2* Z = fft_r22<512, 1>(s0[half], s1[half], j, false);

    size_t fb = (size_t)t * FS;
    #pragma unroll
    for (int sel = 0; sel < 2; sel++) {
        int b = sel ? (512 - j) : j;
        float2 za = Z[b];
        float2 zb = Z[(1024 - b) & 1023];
        float2 Kf = make_float2(0.5f * (za.x + zb.x), 0.5f * (za.y - zb.y));
        float2 dv = make_float2(za.x - zb.x, za.y + zb.y);
        float2 Vf = make_float2(0.5f * dv.y, -0.5f * dv.x);
        g_Kf[fb + b] = Kf;
        g_P [fb + b] = cmul(Kf, Vf);
    }
    if (j == 0) {
        float2 za = Z[256], zb = Z[768];
        float2 Kf = make_float2(0.5f * (za.x + zb.x), 0.5f * (za.y - zb.y));
        float2 dv = make_float2(za.x - zb.x, za.y + zb.y);
        float2 Vf = make_float2(0.5f * dv.y, -0.5f * dv.x);
        g_Kf[fb + 256] = Kf;
        g_P [fb + 256] = cmul(Kf, Vf);
    }
}

// ---------- scan pass 1: intra-chunk cumsum + chunk totals ----------
__global__ void __launch_bounds__(256) scan1() {
    int idx = blockIdx.x * blockDim.x + threadIdx.x;
    int comp  = idx % COMPS;
    int rest  = idx / COMPS;
    int chunk = rest % NCH;
    int b     = rest / NCH;
    float* Pf = (float*)g_P;
    size_t base = (size_t)(b * LL + chunk * CHL) * (FS * 2) + comp;
    float acc = 0.f;
    #pragma unroll 4
    for (int s = 0; s < CHL; s++) {
        acc += Pf[base];
        Pf[base] = acc;
        base += FS * 2;
    }
    g_aux[(b * NCH + chunk) * COMPS + comp] = acc;
}

// ---------- aux exclusive prefix scan (in place) ----------
__global__ void __launch_bounds__(256) aux_scan() {
    int idx = blockIdx.x * blockDim.x + threadIdx.x;
    if (idx >= BB * COMPS) return;
    int b = idx / COMPS, comp = idx % COMPS;
    float run = 0.f;
    for (int c = 0; c < NCH; c++) {
        size_t a = (size_t)(b * NCH + c) * COMPS + comp;
        float v = g_aux[a];
        g_aux[a] = run;
        run += v;
    }
}

// ---------- inv: unbind (+chunk offset), 512-pt radix-2^2 irfft, LN -> bf16 ----------
__global__ void __launch_bounds__(512) inv_kernel(const float* __restrict__ ln_g,
                                                  const float* __restrict__ ln_b) {
    __shared__ float2 sA[4][520];
    __shared__ float2 sB[4][512];
    __shared__ float red[4][8];
    int tid = threadIdx.x;
    int q = tid >> 7, j = tid & 127;
    int t = blockIdx.x * 4 + q;
    size_t fb = (size_t)t * FS;
    int bI = t >> 12;
    int chunk = (t & (LL - 1)) >> 6;
    const float2* aux2 = (const float2*)g_aux + (size_t)(bI * NCH + chunk) * (COMPS/2);

    #pragma unroll
    for (int p = 0; p < 4; p++) {
        int k = j + p * 128;
        float2 kf = g_Kf[fb + k];
        float2 mp = g_P [fb + k];
        float2 av = aux2[k];
        mp.x += av.x; mp.y += av.y;
        sA[q][k] = make_float2(mp.x*kf.x + mp.y*kf.y, mp.y*kf.x - mp.x*kf.y);
    }
    if (j == 0) {
        float2 kf = g_Kf[fb + 512];
        float2 mp = g_P [fb + 512];
        float2 av = aux2[512];
        mp.x += av.x; mp.y += av.y;
        sA[q][512] = make_float2(mp.x*kf.x + mp.y*kf.y, mp.y*kf.x - mp.x*kf.y);
    }
    __syncthreads();

    #pragma unroll
    for (int p = 0; p < 4; p++) {
        int k = j + p * 128;
        float2 Sa = sA[q][k];
        float2 Sb = sA[q][512 - k];
        float2 tw = g_twid[k];
        float twx = tw.x, twy = -tw.y;
        float2 Xe = make_float2(0.5f*(Sa.x + Sb.x), 0.5f*(Sa.y - Sb.y));
        float2 Xd = make_float2(0.5f*(Sa.x - Sb.x), 0.5f*(Sa.y + Sb.y));
        float2 Xo = make_float2(Xd.x*twx - Xd.y*twy, Xd.x*twy + Xd.y*twx);
        sB[q][k] = make_float2(Xe.x - Xo.y, Xe.y + Xo.x);
    }
    __syncthreads();

    float2* R = fft_r22<256, 2>(sB[q], sA[q], j, true);

    float2 Ra = R[j], Rb = R[j + 256], Rc = R[j + 128], Rd = R[j + 384];
    float2 z[4];
    int    zi[4];
    z[0] = cadd(Ra, Rb); zi[0] = j;
    z[1] = csub(Ra, Rb); zi[1] = j + 256;
    z[2] = cadd(Rc, Rd); zi[2] = j + 128;
    z[3] = csub(Rc, Rd); zi[3] = j + 384;

    int pos = (t & (LL - 1)) + 1;
    float scale = rsqrtf((float)pos) * (1.0f / 512.0f);
    float r[8];
    #pragma unroll
    for (int p = 0; p < 4; p++) { r[2*p] = z[p].x * scale; r[2*p+1] = z[p].y * scale; }

    float sm = 0.f, sq = 0.f;
    #pragma unroll
    for (int p = 0; p < 8; p++) { sm += r[p]; sq += r[p]*r[p]; }
    #pragma unroll
    for (int o = 16; o; o >>= 1) {
        sm += __shfl_xor_sync(0xffffffffu, sm, o);
        sq += __shfl_xor_sync(0xffffffffu, sq, o);
    }
    int w4 = (tid >> 5) & 3;
    if ((tid & 31) == 0) { red[q][w4] = sm; red[q][4 + w4] = sq; }
    __syncthreads();
    float smT = 0.f, sqT = 0.f;
    #pragma unroll
    for (int i = 0; i < 4; i++) { smT += red[q][i]; sqT += red[q][4 + i]; }
    float mu  = smT * (1.0f / 1024.0f);
    float var = sqT * (1.0f / 1024.0f) - mu * mu;
    float rstd = rsqrtf(var + 1e-5f);

    __nv_bfloat162* RH = (__nv_bfloat162*)g_rh;
    __nv_bfloat162* RL = (__nv_bfloat162*)g_rl;
    size_t hb = (size_t)t * 512;
    #pragma unroll
    for (int p = 0; p < 4; p++) {
        int idx = zi[p];
        float2 gg = *(const float2*)&ln_g[2*idx];
        float2 bb = *(const float2*)&ln_b[2*idx];
        float y0 = (r[2*p]   - mu) * rstd * gg.x + bb.x;
        float y1 = (r[2*p+1] - mu) * rstd * gg.y + bb.y;
        __nv_bfloat16 h0 = __float2bfloat16_rn(y0);
        __nv_bfloat16 h1 = __float2bfloat16_rn(y1);
        RH[hb + idx] = __nv_bfloat162(h0, h1);
        RL[hb + idx] = __nv_bfloat162(__float2bfloat16_rn(y0 - __bfloat162float(h0)),
                                      __float2bfloat16_rn(y1 - __bfloat162float(h1)));
    }
}

// ---------- launch ----------
extern "C" void kernel_launch(void* const* d_in, const int* in_sizes, int n_in,
                              void* d_out, int out_size) {
    const float* x    = (const float*)d_in[0];
    const float* Wk   = (const float*)d_in[1];
    const float* bk   = (const float*)d_in[2];
    const float* Wv   = (const float*)d_in[3];
    const float* bv   = (const float*)d_in[4];
    const float* ln_g = (const float*)d_in[5];
    const float* ln_b = (const float*)d_in[6];
    const float* Wo   = (const float*)d_in[7];
    const float* bo   = (const float*)d_in[8];
    float* out = (float*)d_out;

    float *keys, *vals;
    __nv_bfloat16 *xh, *xl, *rh, *rl, *wkh, *wkl, *wvh, *wvl, *woh, *wol;
    cudaGetSymbolAddress((void**)&keys, g_keys);
    cudaGetSymbolAddress((void**)&vals, g_vals);
    cudaGetSymbolAddress((void**)&xh, g_xh);   cudaGetSymbolAddress((void**)&xl, g_xl);
    cudaGetSymbolAddress((void**)&rh, g_rh);   cudaGetSymbolAddress((void**)&rl, g_rl);
    cudaGetSymbolAddress((void**)&wkh, g_Wkh); cudaGetSymbolAddress((void**)&wkl, g_Wkl);
    cudaGetSymbolAddress((void**)&wvh, g_Wvh); cudaGetSymbolAddress((void**)&wvl, g_Wvl);
    cudaGetSymbolAddress((void**)&woh, g_Woh); cudaGetSymbolAddress((void**)&wol, g_Wol);

    cudaFuncSetAttribute(gemm_bf16, cudaFuncAttributeMaxDynamicSharedMemorySize, GEMM_SMEM);

    dim3 gg(8, NT / TM);  // (8, 128)

    // launch order arranged so my #4 (= global #6 with the harness's 2
    // pre-launches) is gemm_bf16, for the ncu -s 5 -c 1 capture window.
    conv_split<<<(DD*DD/4 + 255)/256, 256>>>(Wk, wkh, wkl, DD*DD/4);    // 1
    conv_split<<<(NT*DD/4 + 255)/256, 256>>>(x,  xh,  xl,  NT*DD/4);    // 2
    init_twid<<<1, 512>>>();                                            // 3
    gemm_bf16<<<gg, 256, GEMM_SMEM>>>(xh, xl, wkh, wkl, bk, nullptr, keys); // 4  <- profiled
    conv_split<<<(DD*DD/4 + 255)/256, 256>>>(Wv, wvh, wvl, DD*DD/4);    // 5
    gemm_bf16<<<gg, 256, GEMM_SMEM>>>(xh, xl, wvh, wvl, bv, nullptr, vals); // 6
    conv_split<<<(DD*DD/4 + 255)/256, 256>>>(Wo, woh, wol, DD*DD/4);    // 7

    fwd_kernel<<<NT/2, 512>>>();                                        // 8
    scan1<<<(BB * NCH * COMPS) / 256, 256>>>();                         // 9
    aux_scan<<<(BB * COMPS + 255) / 256, 256>>>();                      // 10
    inv_kernel<<<NT/4, 512>>>(ln_g, ln_b);                              // 11

    gemm_bf16<<<gg, 256, GEMM_SMEM>>>(rh, rl, woh, wol, bo, x, out);    // 12
}